// round 16
// baseline (speedup 1.0000x reference)
#include <cuda_runtime.h>
#include <cuda_bf16.h>
#include <mma.h>
using namespace nvcuda;
typedef __nv_bfloat16 bf16;

#define Dm 128
#define NH 8
#define NNODE 40000
#define NEDGE 640000

// ---------------- scratch (static device globals) -----------------------------
__device__ bf16  g_hh[(size_t)NNODE * Dm];     // h = x+t, bf16
__device__ float g_q[(size_t)NNODE * Dm];      // queries fp32
__device__ bf16  g_vh[(size_t)NEDGE * Dm];     // values bf16
__device__ float g_sc[(size_t)NEDGE * NH];     // raw scores
__device__ unsigned g_smax[(size_t)NNODE * NH];
// CSR build
__device__ int g_cnt[NNODE];
__device__ int g_cur[NNODE];
__device__ int g_off[NNODE + 1];
__device__ int g_eid[NEDGE];
// all bf16 weights in one buffer
#define OFF_WR1  0
#define OFF_WLIN 8192
#define OFF_WR2  16384
#define OFF_WQ   32768
#define OFF_WK   49152
#define OFF_WV   65536
#define OFF_WO   81920
#define W_TOTAL  98304
__device__ bf16 g_Wall[W_TOTAL];

// ---------------- helpers ------------------------------------------------------
__device__ __forceinline__ unsigned fenc(float f) {
    unsigned u = __float_as_uint(f);
    return (u & 0x80000000u) ? ~u : (u | 0x80000000u);
}
__device__ __forceinline__ float fdec(unsigned u) {
    return __uint_as_float((u & 0x80000000u) ? (u ^ 0x80000000u) : ~u);
}
#define SMAX_INIT 0x007fffffu

// branch-free shifted softplus: ln2*log2(1+2^(v/ln2)) - ln2
__device__ __forceinline__ float sspf(float v) {
    float t, l;
    asm("ex2.approx.f32 %0, %1;" : "=f"(t) : "f"(v * 1.4426950408889634f));
    asm("lg2.approx.f32 %0, %1;" : "=f"(l) : "f"(1.0f + t));
    return fmaf(0.6931471805599453f, l, -0.6931471805599453f);
}
__device__ __forceinline__ float cutoff(float r) {
    float c = 0.5f * (cosf(r * 0.39269908169872414f) + 1.f);
    return (r < 8.f) ? c : 0.f;
}
__device__ __forceinline__ void st_bf4(bf16* p, float4 v) {
    __nv_bfloat162 a = __floats2bfloat162_rn(v.x, v.y);
    __nv_bfloat162 b = __floats2bfloat162_rn(v.z, v.w);
    uint2 u; u.x = *(unsigned*)&a; u.y = *(unsigned*)&b;
    *(uint2*)p = u;
}

// ---------------- small kernels ------------------------------------------------
__global__ void convert_all_kernel(const float* __restrict__ a0, const float* __restrict__ a1,
                                   const float* __restrict__ a2, const float* __restrict__ a3,
                                   const float* __restrict__ a4, const float* __restrict__ a5,
                                   const float* __restrict__ a6) {
    int i = blockIdx.x * blockDim.x + threadIdx.x;
    if (i >= W_TOTAL) return;
    const float* s; int rel;
    if      (i < 8192)  { s = a0; rel = i; }
    else if (i < 16384) { s = a1; rel = i - 8192; }
    else if (i < 32768) { s = a2; rel = i - 16384; }
    else if (i < 49152) { s = a3; rel = i - 32768; }
    else if (i < 65536) { s = a4; rel = i - 49152; }
    else if (i < 81920) { s = a5; rel = i - 65536; }
    else                { s = a6; rel = i - 81920; }
    g_Wall[i] = __float2bfloat16(s[rel]);
}
__global__ void init_csr_kernel() {
    int gid = blockIdx.x * blockDim.x + threadIdx.x;
    if (gid < NNODE) { g_cnt[gid] = 0; g_cur[gid] = 0; }
}
// h = x+t (bf16) and smax init fused
__global__ void add_h_kernel(const float* __restrict__ x, const float* __restrict__ t) {
    int gid = blockIdx.x * blockDim.x + threadIdx.x;
    if (gid < NNODE * Dm) g_hh[gid] = __float2bfloat16(x[gid] + t[gid]);
    if (gid < NNODE * NH) g_smax[gid] = SMAX_INIT;
}

// ---------------- CSR build ----------------------------------------------------
__global__ void hist_kernel(const int* __restrict__ dst) {
    int e = blockIdx.x * blockDim.x + threadIdx.x;
    if (e < NEDGE) atomicAdd(&g_cnt[dst[e]], 1);
}
__global__ __launch_bounds__(1024) void scan_kernel() {
    __shared__ int part[1024];
    const int C = (NNODE + 1023) / 1024;
    int t = threadIdx.x;
    int base = t * C;
    int s = 0;
    for (int i = 0; i < C; ++i) {
        int idx = base + i;
        if (idx < NNODE) s += g_cnt[idx];
    }
    part[t] = s;
    __syncthreads();
    for (int d = 1; d < 1024; d <<= 1) {
        int v = (t >= d) ? part[t - d] : 0;
        __syncthreads();
        part[t] += v;
        __syncthreads();
    }
    int run = part[t] - s;
    for (int i = 0; i < C; ++i) {
        int idx = base + i;
        if (idx < NNODE) { g_off[idx] = run; run += g_cnt[idx]; }
    }
    if (t == 1023) g_off[NNODE] = run;
}
__global__ void idscatter_kernel(const int* __restrict__ dst) {
    int e = blockIdx.x * blockDim.x + threadIdx.x;
    if (e < NEDGE) {
        int d = dst[e];
        int p = g_off[d] + atomicAdd(&g_cur[d], 1);
        g_eid[p] = e;
    }
}

// ---------------- wmma bf16 machinery ------------------------------------------
typedef wmma::fragment<wmma::matrix_a, 16, 16, 16, bf16, wmma::row_major> HA;
typedef wmma::fragment<wmma::matrix_b, 16, 16, 16, bf16, wmma::row_major> HB;
typedef wmma::fragment<wmma::accumulator, 16, 16, 16, float> HC;

__device__ __forceinline__ void mma_panel_h(const bf16* As, int lda,
                                            const bf16* Bs, int ldb,
                                            HC (&acc)[2][2], int wr, int wc, int ksteps) {
    for (int kk = 0; kk < ksteps; ++kk) {
        HA a[2]; HB b[2];
#pragma unroll
        for (int i = 0; i < 2; ++i)
            wmma::load_matrix_sync(a[i], As + (size_t)(wr * 32 + i * 16) * lda + kk * 16, lda);
#pragma unroll
        for (int j = 0; j < 2; ++j)
            wmma::load_matrix_sync(b[j], Bs + (size_t)(kk * 16) * ldb + wc * 32 + j * 16, ldb);
#pragma unroll
        for (int i = 0; i < 2; ++i)
#pragma unroll
            for (int j = 0; j < 2; ++j) wmma::mma_sync(acc[i][j], a[i], b[j], acc[i][j]);
    }
}
__device__ __forceinline__ void acc_zero(HC (&acc)[2][2]) {
#pragma unroll
    for (int i = 0; i < 2; ++i)
#pragma unroll
        for (int j = 0; j < 2; ++j) wmma::fill_fragment(acc[i][j], 0.f);
}
__device__ __forceinline__ void acc_store(float* S, HC (&acc)[2][2], int wr, int wc) {
#pragma unroll
    for (int i = 0; i < 2; ++i)
#pragma unroll
        for (int j = 0; j < 2; ++j)
            wmma::store_matrix_sync(S + (size_t)(wr * 32 + i * 16) * 132 + wc * 32 + j * 16,
                                    acc[i][j], 132, wmma::mem_row_major);
}
__device__ __forceinline__ void load_weight512(bf16* Bs, const bf16* W, int rows, int tid) {
    int n = rows * 16;
    for (int idx = tid; idx < n; idx += 512) {
        int r = idx >> 4, c8 = (idx & 15) * 8;
        *(uint4*)&Bs[r * 136 + c8] = *(const uint4*)(W + (size_t)r * 128 + c8);
    }
}
// 64-row panel = 1024 uint4 = exactly 2 per thread (512 threads)
__device__ __forceinline__ void ldg_panel(uint4& w0, uint4& w1, const bf16* W, int tid) {
    const uint4* p = (const uint4*)W;
    w0 = p[tid]; w1 = p[tid + 512];
}
__device__ __forceinline__ void sts_panel(bf16* Bs, uint4 w0, uint4 w1, int tid) {
    int r0 = tid >> 4, c0 = (tid & 15) * 8;
    *(uint4*)&Bs[r0 * 136 + c0] = w0;
    int t1 = tid + 512;
    int r1 = t1 >> 4, c1 = (t1 & 15) * 8;
    *(uint4*)&Bs[r1 * 136 + c1] = w1;
}

// ---------------- node GEMM (q projection): out = A@W + bias -------------------
__global__ __launch_bounds__(512)
void node_gemm_h(const bf16* __restrict__ A, const bf16* __restrict__ W,
                 const float* __restrict__ bias, float* __restrict__ C, int M)
{
    extern __shared__ char smraw[];
    float* S  = (float*)smraw;                        // 128*132 f32
    bf16*  As = (bf16*)(smraw + 128 * 132 * 4);       // 128*136
    bf16*  Bs = As + 128 * 136;                       // 128*136
    const int tid = threadIdx.x, wid = tid >> 5;
    const int wr = wid >> 2, wc = wid & 3;
    const int rowBase = blockIdx.x * 128;

#pragma unroll
    for (int p = 0; p < 4; ++p) {
        int idx = tid + p * 512;
        int r = idx >> 4, c8 = (idx & 15) * 8;
        int gr = rowBase + r;
        uint4 v = make_uint4(0, 0, 0, 0);
        if (gr < M) v = *(const uint4*)(A + (size_t)gr * 128 + c8);
        *(uint4*)&As[r * 136 + c8] = v;
    }
    load_weight512(Bs, W, 128, tid);
    __syncthreads();

    HC acc[2][2];
    acc_zero(acc);
    mma_panel_h(As, 136, Bs, 136, acc, wr, wc, 8);
    __syncthreads();
    acc_store(S, acc, wr, wc);
    __syncthreads();

    for (int idx = tid; idx < 4096; idx += 512) {
        int r = idx >> 5, cq = (idx & 31) * 4;
        int gr = rowBase + r;
        if (gr < M) {
            float4 s = *(const float4*)&S[r * 132 + cq];
            s.x += bias[cq]; s.y += bias[cq + 1]; s.z += bias[cq + 2]; s.w += bias[cq + 3];
            *(float4*)(C + (size_t)gr * 128 + cq) = s;
        }
    }
}

// ---------------- fused agg + output GEMM + LN ---------------------------------
// Each block: 128 nodes. Phase A: warp w aggregates nodes [w*8, w*8+8) from CSR
// (softmax-weighted v) straight into As (bf16, same rounding point as before).
// Phase B: GEMM with Wo + bias + residual x + LayerNorm -> out.
__global__ __launch_bounds__(512)
void agg_out_kernel(const float* __restrict__ bo, const float* __restrict__ resid,
                    const float* __restrict__ ln_g, const float* __restrict__ ln_b,
                    float* __restrict__ out)
{
    extern __shared__ char smraw[];
    float* S  = (float*)smraw;                        // 128*132 f32
    bf16*  As = (bf16*)(smraw + 128 * 132 * 4);       // 128*136
    bf16*  Bs = As + 128 * 136;                       // 128*136
    const int tid = threadIdx.x, wid = tid >> 5, lane = tid & 31;
    const int wr = wid >> 2, wc = wid & 3;
    const int rowBase = blockIdx.x * 128;

    // issue Wo weight load first: its latency hides under the gather phase
    load_weight512(Bs, g_Wall + OFF_WO, 128, tid);

    // ---- phase A: per-warp CSR gather aggregation into As ----
    {
        int c4 = lane * 4;
        int h = lane >> 2;
        for (int nn = 0; nn < 8; ++nn) {
            int rl = wid * 8 + nn;
            int node = rowBase + rl;
            float a0 = 0.f, a1 = 0.f, a2 = 0.f, a3 = 0.f, den = 0.f;
            if (node < NNODE) {
                float smax = fdec(g_smax[node * NH + h]);
                int o0 = g_off[node], o1 = g_off[node + 1];
                for (int i = o0; i < o1; ++i) {
                    int e = g_eid[i];
                    float ex = expf(g_sc[(size_t)e * NH + h] - smax);
                    den += ex;
                    uint2 raw = *(const uint2*)(g_vh + (size_t)e * 128 + c4);
                    float2 v0 = __bfloat1622float2(*(__nv_bfloat162*)&raw.x);
                    float2 v1 = __bfloat1622float2(*(__nv_bfloat162*)&raw.y);
                    a0 += ex * v0.x; a1 += ex * v0.y; a2 += ex * v1.x; a3 += ex * v1.y;
                }
            }
            float inv = 1.f / (den + 1e-16f);
            st_bf4(&As[rl * 136 + c4], make_float4(a0 * inv, a1 * inv, a2 * inv, a3 * inv));
        }
    }
    __syncthreads();

    // ---- phase B: GEMM + bias + residual + LN ----
    HC acc[2][2];
    acc_zero(acc);
    mma_panel_h(As, 136, Bs, 136, acc, wr, wc, 8);
    __syncthreads();
    acc_store(S, acc, wr, wc);
    __syncthreads();

    __shared__ float muS[128], invS[128];
    for (int idx = tid; idx < 4096; idx += 512) {
        int r = idx >> 5, cq = (idx & 31) * 4;
        int gr = rowBase + r;
        if (gr < NNODE) {
            float4 s = *(const float4*)&S[r * 132 + cq];
            float4 rr = *(const float4*)(resid + (size_t)gr * 128 + cq);
            s.x += bo[cq] + rr.x;     s.y += bo[cq + 1] + rr.y;
            s.z += bo[cq + 2] + rr.z; s.w += bo[cq + 3] + rr.w;
            *(float4*)&S[r * 132 + cq] = s;
        }
    }
    __syncthreads();
    if (tid < 128) {
        int gr = rowBase + tid;
        if (gr < NNODE) {
            float s = 0.f, q2 = 0.f;
#pragma unroll 4
            for (int c = 0; c < 128; ++c) { float v = S[tid * 132 + c]; s += v; q2 += v * v; }
            float mean = s * (1.f / 128.f);
            float var = q2 * (1.f / 128.f) - mean * mean;
            muS[tid] = mean; invS[tid] = rsqrtf(var + 1e-5f);
        }
    }
    __syncthreads();
    for (int idx = tid; idx < 4096; idx += 512) {
        int r = idx >> 5, cq = (idx & 31) * 4;
        int gr = rowBase + r;
        if (gr < NNODE) {
            float4 s = *(const float4*)&S[r * 132 + cq];
            float4 o;
            o.x = (s.x - muS[r]) * invS[r] * ln_g[cq]     + ln_b[cq];
            o.y = (s.y - muS[r]) * invS[r] * ln_g[cq + 1] + ln_b[cq + 1];
            o.z = (s.z - muS[r]) * invS[r] * ln_g[cq + 2] + ln_b[cq + 2];
            o.w = (s.w - muS[r]) * invS[r] * ln_g[cq + 3] + ln_b[cq + 3];
            *(float4*)(out + (size_t)gr * 128 + cq) = o;
        }
    }
}

// ---------------- mega edge kernel (warp-local epilogues + dbl-buffered W) -----
#define SMO_S 0
#define SMO_F 36864
#define SMO_M 55296
#define SMO_B 90112
#define SMO_TOT 107520
__global__ __launch_bounds__(512, 2)
void edge_fused_kernel(const float* __restrict__ f_ij, const float* __restrict__ r_ij,
                       const int* __restrict__ src, const int* __restrict__ dst,
                       const float* __restrict__ b_r1, const float* __restrict__ b_lin,
                       const float* __restrict__ b_r2,
                       const float* __restrict__ bk, const float* __restrict__ bv)
{
    extern __shared__ char smraw[];
    float* S   = (float*)(smraw + SMO_S);    // 16 warp slots of 16x36 f32
    bf16*  Fs  = (bf16*)(smraw + SMO_F);     // f tile 128x72 (later: Bw1)
    bf16*  Bw1 = (bf16*)(smraw + SMO_F);     // alias (64x136 panel fits in 18432)
    bf16*  Ms  = (bf16*)(smraw + SMO_M);     // 128*136
    bf16*  Bw0 = (bf16*)(smraw + SMO_B);     // 64*136 weight panel
    __shared__ float Ce[128];
    __shared__ int   srcs[128], dsts[128];
    __shared__ float sb1[128], sb2[128], sbk[128], sbv[128];

    const int tid = threadIdx.x, wid = tid >> 5, lane = tid & 31;
    const int wr = wid >> 2, wc = wid & 3;          // 4x4 warp grid, tile 32x32
    const int rowBase = blockIdx.x * 128;           // NEDGE = 5000*128 exactly
    float* Sw = S + wid * 576;                      // private 16x36 slot
    const int lr = lane >> 1, ch = lane & 1;        // epilogue lane mapping
    const int ccol = wc * 32 + ch * 16;             // this lane's 16-col base

    uint4 w0, w1;
    ldg_panel(w0, w1, g_Wall + OFF_WR1, tid);       // P0 = Wr1

    // f tile: 128 x 64 fp32 -> bf16 (2048 float4)
#pragma unroll
    for (int p = 0; p < 4; ++p) {
        int idx = tid + p * 512;
        int r = idx >> 4, cg = (idx & 15) * 4;
        float4 v = *(const float4*)(f_ij + (size_t)(rowBase + r) * 64 + cg);
        st_bf4(&Fs[r * 72 + cg], v);
    }
    if (tid < 128) {
        int e = rowBase + tid;
        Ce[tid] = cutoff(r_ij[e]);
        srcs[tid] = src[e];
        dsts[tid] = dst[e];
        sb1[tid] = b_r1[tid];
        sb2[tid] = b_lin[tid] + b_r2[tid];
        sbk[tid] = bk[tid];
        sbv[tid] = bv[tid];
    }
    sts_panel(Bw0, w0, w1, tid);                    // P0 = Wr1
    ldg_panel(w0, w1, g_Wall + OFF_WLIN, tid);      // P1
    __syncthreads();                                                  // B1

    HC acc[2][2];

    // ---- stage 1: U = ssp(f @ Wr1 + br1) -> Ms ----
    acc_zero(acc);
    mma_panel_h(Fs, 72, Bw0, 136, acc, wr, wc, 4);
    __syncthreads();                                                  // B2 (Bw0 free)
    sts_panel(Bw0, w0, w1, tid);                    // P1 = Wlin
    ldg_panel(w0, w1, g_Wall + OFF_WR2, tid);       // P2
    // warp-local epilogue 1
#pragma unroll
    for (int i = 0; i < 2; ++i) {
        wmma::store_matrix_sync(Sw,      acc[i][0], 36, wmma::mem_row_major);
        wmma::store_matrix_sync(Sw + 16, acc[i][1], 36, wmma::mem_row_major);
        __syncwarp();
        int R = wr * 32 + i * 16 + lr;
#pragma unroll
        for (int j = 0; j < 4; ++j) {
            int c = ccol + j * 4;
            float4 s = *(const float4*)&Sw[lr * 36 + ch * 16 + j * 4];
            float4 u;
            u.x = sspf(s.x + sb1[c]);     u.y = sspf(s.y + sb1[c + 1]);
            u.z = sspf(s.z + sb1[c + 2]); u.w = sspf(s.w + sb1[c + 3]);
            st_bf4(&Ms[R * 136 + c], u);
        }
        __syncwarp();
    }
    __syncthreads();                                                  // B3 (Ms=U, Bw0=Wlin)

    // ---- stage 2: W = f@Wlin + U@Wr2 -> m -> Ms ----
    acc_zero(acc);
    mma_panel_h(Fs, 72, Bw0, 136, acc, wr, wc, 4);  // f@Wlin (LAST use of Fs)
    __syncthreads();                                                  // B4 (Fs dead, Bw0 free)
    sts_panel(Bw1, w0, w1, tid);                    // P2 = Wr2 lo -> Bw1
    ldg_panel(w0, w1, g_Wall + OFF_WR2 + 64 * 128, tid);  // P3
    __syncthreads();                                                  // B5 (Bw1 visible)
    mma_panel_h(Ms, 136, Bw1, 136, acc, wr, wc, 4); // U lo
    sts_panel(Bw0, w0, w1, tid);                    // P3 = Wr2 hi -> Bw0
    ldg_panel(w0, w1, g_Wall + OFF_WK, tid);        // P4
    __syncthreads();                                                  // B6 (Bw0 visible)
    mma_panel_h(Ms + 64, 136, Bw0, 136, acc, wr, wc, 4);
    sts_panel(Bw1, w0, w1, tid);                    // P4 = Wk lo -> Bw1
    ldg_panel(w0, w1, g_Wall + OFF_WK + 64 * 128, tid);   // P5
    __syncthreads();                                                  // B7 (acc done; Bw1 visible)
    // warp-local epilogue 2: m = h[src]*(S + sb2)*Ce -> Ms (uint4 h loads)
#pragma unroll
    for (int i = 0; i < 2; ++i) {
        wmma::store_matrix_sync(Sw,      acc[i][0], 36, wmma::mem_row_major);
        wmma::store_matrix_sync(Sw + 16, acc[i][1], 36, wmma::mem_row_major);
        __syncwarp();
        int R = wr * 32 + i * 16 + lr;
        float ce = Ce[R];
        const bf16* hrow = g_hh + (size_t)srcs[R] * 128 + ccol;
        uint4 hq0 = *(const uint4*)hrow;
        uint4 hq1 = *(const uint4*)(hrow + 8);
        unsigned hw[8] = {hq0.x, hq0.y, hq0.z, hq0.w, hq1.x, hq1.y, hq1.z, hq1.w};
#pragma unroll
        for (int j = 0; j < 4; ++j) {
            int c = ccol + j * 4;
            float4 s = *(const float4*)&Sw[lr * 36 + ch * 16 + j * 4];
            float2 h0 = __bfloat1622float2(*(__nv_bfloat162*)&hw[j * 2]);
            float2 h1 = __bfloat1622float2(*(__nv_bfloat162*)&hw[j * 2 + 1]);
            float4 m;
            m.x = h0.x * (s.x + sb2[c])     * ce;
            m.y = h0.y * (s.y + sb2[c + 1]) * ce;
            m.z = h1.x * (s.z + sb2[c + 2]) * ce;
            m.w = h1.y * (s.w + sb2[c + 3]) * ce;
            st_bf4(&Ms[R * 136 + c], m);
        }
        __syncwarp();
    }
    __syncthreads();                                                  // B8 (Ms=m visible)

    // ---- k stage: k = m@Wk ----
    acc_zero(acc);
    mma_panel_h(Ms, 136, Bw1, 136, acc, wr, wc, 4); // m lo @ Wk lo
    sts_panel(Bw0, w0, w1, tid);                    // P5 = Wk hi -> Bw0
    ldg_panel(w0, w1, g_Wall + OFF_WV, tid);        // P6
    __syncthreads();                                                  // B9 (Bw0 visible)
    mma_panel_h(Ms + 64, 136, Bw0, 136, acc, wr, wc, 4);
    sts_panel(Bw1, w0, w1, tid);                    // P6 = Wv lo -> Bw1
    ldg_panel(w0, w1, g_Wall + OFF_WV + 64 * 128, tid);   // P7
    // warp-local epilogue 3 BEFORE barrier: per (row, head) score dot
#pragma unroll
    for (int i = 0; i < 2; ++i) {
        wmma::store_matrix_sync(Sw,      acc[i][0], 36, wmma::mem_row_major);
        wmma::store_matrix_sync(Sw + 16, acc[i][1], 36, wmma::mem_row_major);
        __syncwarp();
        int R = wr * 32 + i * 16 + lr;
        int h = wc * 2 + ch;
        int d = dsts[R];
        const float* kp = &Sw[lr * 36 + ch * 16];
        const float4* qp = (const float4*)(g_q + (size_t)d * 128 + h * 16);
        const float* bb = &sbk[h * 16];
        float s = 0.f;
#pragma unroll
        for (int j = 0; j < 4; ++j) {
            float4 qv = qp[j];
            s += (kp[j * 4 + 0] + bb[j * 4 + 0]) * qv.x;
            s += (kp[j * 4 + 1] + bb[j * 4 + 1]) * qv.y;
            s += (kp[j * 4 + 2] + bb[j * 4 + 2]) * qv.z;
            s += (kp[j * 4 + 3] + bb[j * 4 + 3]) * qv.w;
        }
        s *= 0.25f;
        g_sc[(size_t)(rowBase + R) * NH + h] = s;
        atomicMax(&g_smax[d * NH + h], fenc(s));
        __syncwarp();
    }
    __syncthreads();                                                  // B10 (Bw1=Wv lo visible)

    // ---- v stage: v = m@Wv + bv -> g_vh ----
    acc_zero(acc);
    mma_panel_h(Ms, 136, Bw1, 136, acc, wr, wc, 4); // m lo @ Wv lo
    sts_panel(Bw0, w0, w1, tid);                    // P7 = Wv hi -> Bw0
    __syncthreads();                                                  // B11 (Bw0 visible)
    mma_panel_h(Ms + 64, 136, Bw0, 136, acc, wr, wc, 4);
    // warp-local epilogue 4
#pragma unroll
    for (int i = 0; i < 2; ++i) {
        wmma::store_matrix_sync(Sw,      acc[i][0], 36, wmma::mem_row_major);
        wmma::store_matrix_sync(Sw + 16, acc[i][1], 36, wmma::mem_row_major);
        __syncwarp();
        int R = wr * 32 + i * 16 + lr;
#pragma unroll
        for (int j = 0; j < 4; ++j) {
            int c = ccol + j * 4;
            float4 s = *(const float4*)&Sw[lr * 36 + ch * 16 + j * 4];
            s.x += sbv[c]; s.y += sbv[c + 1]; s.z += sbv[c + 2]; s.w += sbv[c + 3];
            st_bf4(&g_vh[(size_t)(rowBase + R) * 128 + c], s);
        }
        __syncwarp();
    }
}

// ---------------- launch --------------------------------------------------------
extern "C" void kernel_launch(void* const* d_in, const int* in_sizes, int n_in,
                              void* d_out, int out_size) {
    const float* x     = (const float*)d_in[0];
    const float* t     = (const float*)d_in[1];
    const float* f_ij  = (const float*)d_in[2];
    const float* r_ij  = (const float*)d_in[3];
    const int*   src   = (const int*)d_in[4];
    const int*   dst   = (const int*)d_in[5];
    const float* W_lin = (const float*)d_in[6];
    const float* b_lin = (const float*)d_in[7];
    const float* W_r1  = (const float*)d_in[8];
    const float* b_r1  = (const float*)d_in[9];
    const float* W_r2  = (const float*)d_in[10];
    const float* b_r2  = (const float*)d_in[11];
    const float* Wq    = (const float*)d_in[12];
    const float* bq    = (const float*)d_in[13];
    const float* Wk    = (const float*)d_in[14];
    const float* bk    = (const float*)d_in[15];
    const float* Wv    = (const float*)d_in[16];
    const float* bv    = (const float*)d_in[17];
    const float* Wo    = (const float*)d_in[18];
    const float* bo    = (const float*)d_in[19];
    const float* ln_g  = (const float*)d_in[20];
    const float* ln_b  = (const float*)d_in[21];
    float* out = (float*)d_out;

    bf16 *pWall, *phh;
    float *pq;
    cudaGetSymbolAddress((void**)&pWall, g_Wall);
    cudaGetSymbolAddress((void**)&phh, g_hh);
    cudaGetSymbolAddress((void**)&pq,  g_q);

    static cudaStream_t s_side = nullptr;
    static cudaEvent_t ev_fork = nullptr, ev_join = nullptr;
    if (s_side == nullptr) {
        cudaStreamCreateWithFlags(&s_side, cudaStreamNonBlocking);
        cudaEventCreateWithFlags(&ev_fork, cudaEventDisableTiming);
        cudaEventCreateWithFlags(&ev_join, cudaEventDisableTiming);
    }

    const int SM_NODE = 128 * 132 * 4 + 2 * (128 * 136 * 2);   // 137216
    cudaFuncSetAttribute((const void*)node_gemm_h,       cudaFuncAttributeMaxDynamicSharedMemorySize, SM_NODE);
    cudaFuncSetAttribute((const void*)agg_out_kernel,    cudaFuncAttributeMaxDynamicSharedMemorySize, SM_NODE);
    cudaFuncSetAttribute((const void*)edge_fused_kernel, cudaFuncAttributeMaxDynamicSharedMemorySize, SMO_TOT);

    const int TB = 256;
    int gridN  = (NNODE * Dm + TB - 1) / TB;
    int gridE  = (NEDGE + TB - 1) / TB;
    int gemmE  = NEDGE / 128;           // 5000
    int gemmN  = (NNODE + 127) / 128;   // 313

    // ---- main stream (round-8 proven schedule) ----
    convert_all_kernel<<<W_TOTAL / 512, 512>>>(W_r1, W_lin, W_r2, Wq, Wk, Wv, Wo);
    add_h_kernel<<<gridN, TB>>>(x, t);           // also inits g_smax

    // ---- fork: CSR build on side stream (independent of GEMM chain) ----
    cudaEventRecord(ev_fork, 0);
    cudaStreamWaitEvent(s_side, ev_fork, 0);
    init_csr_kernel<<<(NNODE + TB - 1) / TB, TB, 0, s_side>>>();
    hist_kernel<<<gridE, TB, 0, s_side>>>(dst);
    scan_kernel<<<1, 1024, 0, s_side>>>();
    idscatter_kernel<<<gridE, TB, 0, s_side>>>(dst);
    cudaEventRecord(ev_join, s_side);

    // ---- main continues ----
    node_gemm_h<<<gemmN, 512, SM_NODE>>>(phh, pWall + OFF_WQ, bq, pq, NNODE);
    edge_fused_kernel<<<gemmE, 512, SMO_TOT>>>(f_ij, r_ij, src, dst,
                                               b_r1, b_lin, b_r2, bk, bv);

    // ---- join, then fused aggregation + output GEMM + LN ----
    cudaStreamWaitEvent(0, ev_join, 0);
    agg_out_kernel<<<gemmN, 512, SM_NODE>>>(bo, x, ln_g, ln_b, out);
}

// round 17
// speedup vs baseline: 1.0755x; 1.0755x over previous
#include <cuda_runtime.h>
#include <cuda_bf16.h>
#include <mma.h>
using namespace nvcuda;
typedef __nv_bfloat16 bf16;

#define Dm 128
#define NH 8
#define NNODE 40000
#define NEDGE 640000

// ---------------- scratch (static device globals) -----------------------------
__device__ bf16  g_hh[(size_t)NNODE * Dm];     // h = x+t, bf16
__device__ float g_q[(size_t)NNODE * Dm];      // queries fp32
__device__ bf16  g_vh[(size_t)NEDGE * Dm];     // values bf16
__device__ float g_sc[(size_t)NEDGE * NH];     // raw scores
__device__ unsigned g_smax[(size_t)NNODE * NH];
__device__ bf16  g_aggh[(size_t)NNODE * Dm];   // aggregated output, bf16
// CSR build
__device__ int g_cnt[NNODE];
__device__ int g_cur[NNODE];
__device__ int g_off[NNODE + 1];
__device__ int g_eid[NEDGE];
// all bf16 weights in one buffer
#define OFF_WR1  0
#define OFF_WLIN 8192
#define OFF_WR2  16384
#define OFF_WQ   32768
#define OFF_WK   49152
#define OFF_WV   65536
#define OFF_WO   81920
#define W_TOTAL  98304
__device__ bf16 g_Wall[W_TOTAL];

// ---------------- helpers ------------------------------------------------------
__device__ __forceinline__ unsigned fenc(float f) {
    unsigned u = __float_as_uint(f);
    return (u & 0x80000000u) ? ~u : (u | 0x80000000u);
}
__device__ __forceinline__ float fdec(unsigned u) {
    return __uint_as_float((u & 0x80000000u) ? (u ^ 0x80000000u) : ~u);
}
#define SMAX_INIT 0x007fffffu

// branch-free shifted softplus: ln2*log2(1+2^(v/ln2)) - ln2
__device__ __forceinline__ float sspf(float v) {
    float t, l;
    asm("ex2.approx.f32 %0, %1;" : "=f"(t) : "f"(v * 1.4426950408889634f));
    asm("lg2.approx.f32 %0, %1;" : "=f"(l) : "f"(1.0f + t));
    return fmaf(0.6931471805599453f, l, -0.6931471805599453f);
}
__device__ __forceinline__ float cutoff(float r) {
    float c = 0.5f * (cosf(r * 0.39269908169872414f) + 1.f);
    return (r < 8.f) ? c : 0.f;
}
__device__ __forceinline__ void st_bf4(bf16* p, float4 v) {
    __nv_bfloat162 a = __floats2bfloat162_rn(v.x, v.y);
    __nv_bfloat162 b = __floats2bfloat162_rn(v.z, v.w);
    uint2 u; u.x = *(unsigned*)&a; u.y = *(unsigned*)&b;
    *(uint2*)p = u;
}

// ---------------- small kernels ------------------------------------------------
__global__ void convert_all_kernel(const float* __restrict__ a0, const float* __restrict__ a1,
                                   const float* __restrict__ a2, const float* __restrict__ a3,
                                   const float* __restrict__ a4, const float* __restrict__ a5,
                                   const float* __restrict__ a6) {
    int i = blockIdx.x * blockDim.x + threadIdx.x;
    if (i >= W_TOTAL) return;
    const float* s; int rel;
    if      (i < 8192)  { s = a0; rel = i; }
    else if (i < 16384) { s = a1; rel = i - 8192; }
    else if (i < 32768) { s = a2; rel = i - 16384; }
    else if (i < 49152) { s = a3; rel = i - 32768; }
    else if (i < 65536) { s = a4; rel = i - 49152; }
    else if (i < 81920) { s = a5; rel = i - 65536; }
    else                { s = a6; rel = i - 81920; }
    g_Wall[i] = __float2bfloat16(s[rel]);
}
__global__ void init_csr_kernel() {
    int gid = blockIdx.x * blockDim.x + threadIdx.x;
    if (gid < NNODE) { g_cnt[gid] = 0; g_cur[gid] = 0; }
}
// h = x+t (bf16) and smax init fused
__global__ void add_h_kernel(const float* __restrict__ x, const float* __restrict__ t) {
    int gid = blockIdx.x * blockDim.x + threadIdx.x;
    if (gid < NNODE * Dm) g_hh[gid] = __float2bfloat16(x[gid] + t[gid]);
    if (gid < NNODE * NH) g_smax[gid] = SMAX_INIT;
}

// ---------------- CSR build ----------------------------------------------------
__global__ void hist_kernel(const int* __restrict__ dst) {
    int e = blockIdx.x * blockDim.x + threadIdx.x;
    if (e < NEDGE) atomicAdd(&g_cnt[dst[e]], 1);
}
__global__ __launch_bounds__(1024) void scan_kernel() {
    __shared__ int part[1024];
    const int C = (NNODE + 1023) / 1024;
    int t = threadIdx.x;
    int base = t * C;
    int s = 0;
    for (int i = 0; i < C; ++i) {
        int idx = base + i;
        if (idx < NNODE) s += g_cnt[idx];
    }
    part[t] = s;
    __syncthreads();
    for (int d = 1; d < 1024; d <<= 1) {
        int v = (t >= d) ? part[t - d] : 0;
        __syncthreads();
        part[t] += v;
        __syncthreads();
    }
    int run = part[t] - s;
    for (int i = 0; i < C; ++i) {
        int idx = base + i;
        if (idx < NNODE) { g_off[idx] = run; run += g_cnt[idx]; }
    }
    if (t == 1023) g_off[NNODE] = run;
}
__global__ void idscatter_kernel(const int* __restrict__ dst) {
    int e = blockIdx.x * blockDim.x + threadIdx.x;
    if (e < NEDGE) {
        int d = dst[e];
        int p = g_off[d] + atomicAdd(&g_cur[d], 1);
        g_eid[p] = e;
    }
}

// ---------------- wmma bf16 machinery ------------------------------------------
typedef wmma::fragment<wmma::matrix_a, 16, 16, 16, bf16, wmma::row_major> HA;
typedef wmma::fragment<wmma::matrix_b, 16, 16, 16, bf16, wmma::row_major> HB;
typedef wmma::fragment<wmma::accumulator, 16, 16, 16, float> HC;

__device__ __forceinline__ void mma_panel_h(const bf16* As, int lda,
                                            const bf16* Bs, int ldb,
                                            HC (&acc)[2][2], int wr, int wc, int ksteps) {
    for (int kk = 0; kk < ksteps; ++kk) {
        HA a[2]; HB b[2];
#pragma unroll
        for (int i = 0; i < 2; ++i)
            wmma::load_matrix_sync(a[i], As + (size_t)(wr * 32 + i * 16) * lda + kk * 16, lda);
#pragma unroll
        for (int j = 0; j < 2; ++j)
            wmma::load_matrix_sync(b[j], Bs + (size_t)(kk * 16) * ldb + wc * 32 + j * 16, ldb);
#pragma unroll
        for (int i = 0; i < 2; ++i)
#pragma unroll
            for (int j = 0; j < 2; ++j) wmma::mma_sync(acc[i][j], a[i], b[j], acc[i][j]);
    }
}
__device__ __forceinline__ void acc_zero(HC (&acc)[2][2]) {
#pragma unroll
    for (int i = 0; i < 2; ++i)
#pragma unroll
        for (int j = 0; j < 2; ++j) wmma::fill_fragment(acc[i][j], 0.f);
}
__device__ __forceinline__ void acc_store(float* S, HC (&acc)[2][2], int wr, int wc) {
#pragma unroll
    for (int i = 0; i < 2; ++i)
#pragma unroll
        for (int j = 0; j < 2; ++j)
            wmma::store_matrix_sync(S + (size_t)(wr * 32 + i * 16) * 132 + wc * 32 + j * 16,
                                    acc[i][j], 132, wmma::mem_row_major);
}
__device__ __forceinline__ void load_weight512(bf16* Bs, const bf16* W, int rows, int tid) {
    int n = rows * 16;
    for (int idx = tid; idx < n; idx += 512) {
        int r = idx >> 4, c8 = (idx & 15) * 8;
        *(uint4*)&Bs[r * 136 + c8] = *(const uint4*)(W + (size_t)r * 128 + c8);
    }
}
// 64-row panel = 1024 uint4 = exactly 2 per thread (512 threads)
__device__ __forceinline__ void ldg_panel(uint4& w0, uint4& w1, const bf16* W, int tid) {
    const uint4* p = (const uint4*)W;
    w0 = p[tid]; w1 = p[tid + 512];
}
__device__ __forceinline__ void sts_panel(bf16* Bs, uint4 w0, uint4 w1, int tid) {
    int r0 = tid >> 4, c0 = (tid & 15) * 8;
    *(uint4*)&Bs[r0 * 136 + c0] = w0;
    int t1 = tid + 512;
    int r1 = t1 >> 4, c1 = (t1 & 15) * 8;
    *(uint4*)&Bs[r1 * 136 + c1] = w1;
}

// ---------------- node GEMM: MODE 0 = +bias; MODE 3 = resid+LN -----------------
template <int MODE, bool AB16>
__global__ __launch_bounds__(512)
void node_gemm_h(const void* __restrict__ Ain, const bf16* __restrict__ W,
                 const float* __restrict__ bias, float* __restrict__ C, int M,
                 const float* __restrict__ resid,
                 const float* __restrict__ ln_g, const float* __restrict__ ln_b)
{
    extern __shared__ char smraw[];
    float* S  = (float*)smraw;                        // 128*132 f32
    bf16*  As = (bf16*)(smraw + 128 * 132 * 4);       // 128*136
    bf16*  Bs = As + 128 * 136;                       // 128*136
    const int tid = threadIdx.x, wid = tid >> 5;
    const int wr = wid >> 2, wc = wid & 3;
    const int rowBase = blockIdx.x * 128;

    if constexpr (AB16) {
        const bf16* A = (const bf16*)Ain;
#pragma unroll
        for (int p = 0; p < 4; ++p) {
            int idx = tid + p * 512;
            int r = idx >> 4, c8 = (idx & 15) * 8;
            int gr = rowBase + r;
            uint4 v = make_uint4(0, 0, 0, 0);
            if (gr < M) v = *(const uint4*)(A + (size_t)gr * 128 + c8);
            *(uint4*)&As[r * 136 + c8] = v;
        }
    } else {
        const float* A = (const float*)Ain;
#pragma unroll
        for (int p = 0; p < 8; ++p) {
            int idx = tid + p * 512;
            int r = idx >> 5, cg = (idx & 31) * 4;
            int gr = rowBase + r;
            float4 v = make_float4(0.f, 0.f, 0.f, 0.f);
            if (gr < M) v = *(const float4*)(A + (size_t)gr * 128 + cg);
            st_bf4(&As[r * 136 + cg], v);
        }
    }
    load_weight512(Bs, W, 128, tid);
    __syncthreads();

    HC acc[2][2];
    acc_zero(acc);
    mma_panel_h(As, 136, Bs, 136, acc, wr, wc, 8);
    __syncthreads();
    acc_store(S, acc, wr, wc);
    __syncthreads();

    if constexpr (MODE == 0) {
        for (int idx = tid; idx < 4096; idx += 512) {
            int r = idx >> 5, cq = (idx & 31) * 4;
            int gr = rowBase + r;
            if (gr < M) {
                float4 s = *(const float4*)&S[r * 132 + cq];
                s.x += bias[cq]; s.y += bias[cq + 1]; s.z += bias[cq + 2]; s.w += bias[cq + 3];
                *(float4*)(C + (size_t)gr * 128 + cq) = s;
            }
        }
    } else {
        __shared__ float muS[128], invS[128];
        for (int idx = tid; idx < 4096; idx += 512) {
            int r = idx >> 5, cq = (idx & 31) * 4;
            int gr = rowBase + r;
            if (gr < M) {
                float4 s = *(const float4*)&S[r * 132 + cq];
                float4 rr = *(const float4*)(resid + (size_t)gr * 128 + cq);
                s.x += bias[cq] + rr.x;     s.y += bias[cq + 1] + rr.y;
                s.z += bias[cq + 2] + rr.z; s.w += bias[cq + 3] + rr.w;
                *(float4*)&S[r * 132 + cq] = s;
            }
        }
        __syncthreads();
        if (tid < 128) {
            int gr = rowBase + tid;
            if (gr < M) {
                float s = 0.f, q2 = 0.f;
#pragma unroll 4
                for (int c = 0; c < 128; ++c) { float v = S[tid * 132 + c]; s += v; q2 += v * v; }
                float mean = s * (1.f / 128.f);
                float var = q2 * (1.f / 128.f) - mean * mean;
                muS[tid] = mean; invS[tid] = rsqrtf(var + 1e-5f);
            }
        }
        __syncthreads();
        for (int idx = tid; idx < 4096; idx += 512) {
            int r = idx >> 5, cq = (idx & 31) * 4;
            int gr = rowBase + r;
            if (gr < M) {
                float4 s = *(const float4*)&S[r * 132 + cq];
                float4 o;
                o.x = (s.x - muS[r]) * invS[r] * ln_g[cq]     + ln_b[cq];
                o.y = (s.y - muS[r]) * invS[r] * ln_g[cq + 1] + ln_b[cq + 1];
                o.z = (s.z - muS[r]) * invS[r] * ln_g[cq + 2] + ln_b[cq + 2];
                o.w = (s.w - muS[r]) * invS[r] * ln_g[cq + 3] + ln_b[cq + 3];
                *(float4*)(C + (size_t)gr * 128 + cq) = o;
            }
        }
    }
}

// ---------------- mega edge kernel (warp-local epilogues + dbl-buffered W) -----
#define SMO_S 0
#define SMO_F 36864
#define SMO_M 55296
#define SMO_B 90112
#define SMO_TOT 107520
__global__ __launch_bounds__(512, 2)
void edge_fused_kernel(const float* __restrict__ f_ij, const float* __restrict__ r_ij,
                       const int* __restrict__ src, const int* __restrict__ dst,
                       const float* __restrict__ b_r1, const float* __restrict__ b_lin,
                       const float* __restrict__ b_r2,
                       const float* __restrict__ bk, const float* __restrict__ bv)
{
    extern __shared__ char smraw[];
    float* S   = (float*)(smraw + SMO_S);    // 16 warp slots of 16x36 f32
    bf16*  Fs  = (bf16*)(smraw + SMO_F);     // f tile 128x72 (later: Bw1)
    bf16*  Bw1 = (bf16*)(smraw + SMO_F);     // alias (64x136 panel fits in 18432)
    bf16*  Ms  = (bf16*)(smraw + SMO_M);     // 128*136
    bf16*  Bw0 = (bf16*)(smraw + SMO_B);     // 64*136 weight panel
    __shared__ float Ce[128];
    __shared__ int   srcs[128], dsts[128];
    __shared__ float sb1[128], sb2[128], sbk[128], sbv[128];

    const int tid = threadIdx.x, wid = tid >> 5, lane = tid & 31;
    const int wr = wid >> 2, wc = wid & 3;          // 4x4 warp grid, tile 32x32
    const int rowBase = blockIdx.x * 128;           // NEDGE = 5000*128 exactly
    float* Sw = S + wid * 576;                      // private 16x36 slot
    const int lr = lane >> 1, ch = lane & 1;        // epilogue lane mapping
    const int ccol = wc * 32 + ch * 16;             // this lane's 16-col base

    uint4 w0, w1;
    ldg_panel(w0, w1, g_Wall + OFF_WR1, tid);       // P0 = Wr1

    // f tile: 128 x 64 fp32 -> bf16 (2048 float4)
#pragma unroll
    for (int p = 0; p < 4; ++p) {
        int idx = tid + p * 512;
        int r = idx >> 4, cg = (idx & 15) * 4;
        float4 v = *(const float4*)(f_ij + (size_t)(rowBase + r) * 64 + cg);
        st_bf4(&Fs[r * 72 + cg], v);
    }
    if (tid < 128) {
        int e = rowBase + tid;
        Ce[tid] = cutoff(r_ij[e]);
        srcs[tid] = src[e];
        dsts[tid] = dst[e];
        sb1[tid] = b_r1[tid];
        sb2[tid] = b_lin[tid] + b_r2[tid];
        sbk[tid] = bk[tid];
        sbv[tid] = bv[tid];
    }
    sts_panel(Bw0, w0, w1, tid);                    // P0 = Wr1
    ldg_panel(w0, w1, g_Wall + OFF_WLIN, tid);      // P1
    __syncthreads();                                                  // B1

    HC acc[2][2];

    // ---- stage 1: U = ssp(f @ Wr1 + br1) -> Ms ----
    acc_zero(acc);
    mma_panel_h(Fs, 72, Bw0, 136, acc, wr, wc, 4);
    __syncthreads();                                                  // B2 (Bw0 free)
    sts_panel(Bw0, w0, w1, tid);                    // P1 = Wlin
    ldg_panel(w0, w1, g_Wall + OFF_WR2, tid);       // P2
    // warp-local epilogue 1
#pragma unroll
    for (int i = 0; i < 2; ++i) {
        wmma::store_matrix_sync(Sw,      acc[i][0], 36, wmma::mem_row_major);
        wmma::store_matrix_sync(Sw + 16, acc[i][1], 36, wmma::mem_row_major);
        __syncwarp();
        int R = wr * 32 + i * 16 + lr;
#pragma unroll
        for (int j = 0; j < 4; ++j) {
            int c = ccol + j * 4;
            float4 s = *(const float4*)&Sw[lr * 36 + ch * 16 + j * 4];
            float4 u;
            u.x = sspf(s.x + sb1[c]);     u.y = sspf(s.y + sb1[c + 1]);
            u.z = sspf(s.z + sb1[c + 2]); u.w = sspf(s.w + sb1[c + 3]);
            st_bf4(&Ms[R * 136 + c], u);
        }
        __syncwarp();
    }
    __syncthreads();                                                  // B3 (Ms=U, Bw0=Wlin)

    // ---- stage 2: W = f@Wlin + U@Wr2 -> m -> Ms ----
    acc_zero(acc);
    mma_panel_h(Fs, 72, Bw0, 136, acc, wr, wc, 4);  // f@Wlin (LAST use of Fs)
    __syncthreads();                                                  // B4 (Fs dead, Bw0 free)
    sts_panel(Bw1, w0, w1, tid);                    // P2 = Wr2 lo -> Bw1
    ldg_panel(w0, w1, g_Wall + OFF_WR2 + 64 * 128, tid);  // P3
    __syncthreads();                                                  // B5 (Bw1 visible)
    mma_panel_h(Ms, 136, Bw1, 136, acc, wr, wc, 4); // U lo
    sts_panel(Bw0, w0, w1, tid);                    // P3 = Wr2 hi -> Bw0
    ldg_panel(w0, w1, g_Wall + OFF_WK, tid);        // P4
    __syncthreads();                                                  // B6 (Bw0 visible)
    mma_panel_h(Ms + 64, 136, Bw0, 136, acc, wr, wc, 4);
    sts_panel(Bw1, w0, w1, tid);                    // P4 = Wk lo -> Bw1
    ldg_panel(w0, w1, g_Wall + OFF_WK + 64 * 128, tid);   // P5
    __syncthreads();                                                  // B7 (acc done; Bw1 visible)
    // warp-local epilogue 2: m = h[src]*(S + sb2)*Ce -> Ms (uint4 h loads)
#pragma unroll
    for (int i = 0; i < 2; ++i) {
        wmma::store_matrix_sync(Sw,      acc[i][0], 36, wmma::mem_row_major);
        wmma::store_matrix_sync(Sw + 16, acc[i][1], 36, wmma::mem_row_major);
        __syncwarp();
        int R = wr * 32 + i * 16 + lr;
        float ce = Ce[R];
        const bf16* hrow = g_hh + (size_t)srcs[R] * 128 + ccol;
        uint4 hq0 = *(const uint4*)hrow;
        uint4 hq1 = *(const uint4*)(hrow + 8);
        unsigned hw[8] = {hq0.x, hq0.y, hq0.z, hq0.w, hq1.x, hq1.y, hq1.z, hq1.w};
#pragma unroll
        for (int j = 0; j < 4; ++j) {
            int c = ccol + j * 4;
            float4 s = *(const float4*)&Sw[lr * 36 + ch * 16 + j * 4];
            float2 h0 = __bfloat1622float2(*(__nv_bfloat162*)&hw[j * 2]);
            float2 h1 = __bfloat1622float2(*(__nv_bfloat162*)&hw[j * 2 + 1]);
            float4 m;
            m.x = h0.x * (s.x + sb2[c])     * ce;
            m.y = h0.y * (s.y + sb2[c + 1]) * ce;
            m.z = h1.x * (s.z + sb2[c + 2]) * ce;
            m.w = h1.y * (s.w + sb2[c + 3]) * ce;
            st_bf4(&Ms[R * 136 + c], m);
        }
        __syncwarp();
    }
    __syncthreads();                                                  // B8 (Ms=m visible)

    // ---- k stage: k = m@Wk ----
    acc_zero(acc);
    mma_panel_h(Ms, 136, Bw1, 136, acc, wr, wc, 4); // m lo @ Wk lo
    sts_panel(Bw0, w0, w1, tid);                    // P5 = Wk hi -> Bw0
    ldg_panel(w0, w1, g_Wall + OFF_WV, tid);        // P6
    __syncthreads();                                                  // B9 (Bw0 visible)
    mma_panel_h(Ms + 64, 136, Bw0, 136, acc, wr, wc, 4);
    sts_panel(Bw1, w0, w1, tid);                    // P6 = Wv lo -> Bw1
    ldg_panel(w0, w1, g_Wall + OFF_WV + 64 * 128, tid);   // P7
    // warp-local epilogue 3 BEFORE barrier: per (row, head) score dot
#pragma unroll
    for (int i = 0; i < 2; ++i) {
        wmma::store_matrix_sync(Sw,      acc[i][0], 36, wmma::mem_row_major);
        wmma::store_matrix_sync(Sw + 16, acc[i][1], 36, wmma::mem_row_major);
        __syncwarp();
        int R = wr * 32 + i * 16 + lr;
        int h = wc * 2 + ch;
        int d = dsts[R];
        const float* kp = &Sw[lr * 36 + ch * 16];
        const float4* qp = (const float4*)(g_q + (size_t)d * 128 + h * 16);
        const float* bb = &sbk[h * 16];
        float s = 0.f;
#pragma unroll
        for (int j = 0; j < 4; ++j) {
            float4 qv = qp[j];
            s += (kp[j * 4 + 0] + bb[j * 4 + 0]) * qv.x;
            s += (kp[j * 4 + 1] + bb[j * 4 + 1]) * qv.y;
            s += (kp[j * 4 + 2] + bb[j * 4 + 2]) * qv.z;
            s += (kp[j * 4 + 3] + bb[j * 4 + 3]) * qv.w;
        }
        s *= 0.25f;
        g_sc[(size_t)(rowBase + R) * NH + h] = s;
        atomicMax(&g_smax[d * NH + h], fenc(s));
        __syncwarp();
    }
    __syncthreads();                                                  // B10 (Bw1=Wv lo visible)

    // ---- v stage: v = m@Wv + bv -> g_vh ----
    acc_zero(acc);
    mma_panel_h(Ms, 136, Bw1, 136, acc, wr, wc, 4); // m lo @ Wv lo
    sts_panel(Bw0, w0, w1, tid);                    // P7 = Wv hi -> Bw0
    __syncthreads();                                                  // B11 (Bw0 visible)
    mma_panel_h(Ms + 64, 136, Bw0, 136, acc, wr, wc, 4);
    // warp-local epilogue 4
#pragma unroll
    for (int i = 0; i < 2; ++i) {
        wmma::store_matrix_sync(Sw,      acc[i][0], 36, wmma::mem_row_major);
        wmma::store_matrix_sync(Sw + 16, acc[i][1], 36, wmma::mem_row_major);
        __syncwarp();
        int R = wr * 32 + i * 16 + lr;
#pragma unroll
        for (int j = 0; j < 4; ++j) {
            int c = ccol + j * 4;
            float4 s = *(const float4*)&Sw[lr * 36 + ch * 16 + j * 4];
            s.x += sbv[c]; s.y += sbv[c + 1]; s.z += sbv[c + 2]; s.w += sbv[c + 3];
            st_bf4(&g_vh[(size_t)(rowBase + R) * 128 + c], s);
        }
        __syncwarp();
    }
}

// ---------------- gather aggregation: one warp per node, 2x unrolled -----------
__global__ __launch_bounds__(256)
void agg_kernel() {
    int w = (blockIdx.x * blockDim.x + threadIdx.x) >> 5;
    if (w >= NNODE) return;
    int l = threadIdx.x & 31;
    int c4 = l * 4;
    int h = l >> 2;
    float smax = fdec(g_smax[w * NH + h]);
    int o0 = g_off[w], o1 = g_off[w + 1];
    float a0 = 0.f, a1 = 0.f, a2 = 0.f, a3 = 0.f, den = 0.f;
    int i = o0;
    for (; i + 2 <= o1; i += 2) {
        int e0 = g_eid[i], e1 = g_eid[i + 1];
        float s0 = g_sc[(size_t)e0 * NH + h];
        float s1 = g_sc[(size_t)e1 * NH + h];
        uint2 r0 = *(const uint2*)(g_vh + (size_t)e0 * 128 + c4);
        uint2 r1 = *(const uint2*)(g_vh + (size_t)e1 * 128 + c4);
        float ex0 = expf(s0 - smax), ex1 = expf(s1 - smax);
        den += ex0 + ex1;
        float2 p0 = __bfloat1622float2(*(__nv_bfloat162*)&r0.x);
        float2 p1 = __bfloat1622float2(*(__nv_bfloat162*)&r0.y);
        float2 q0 = __bfloat1622float2(*(__nv_bfloat162*)&r1.x);
        float2 q1 = __bfloat1622float2(*(__nv_bfloat162*)&r1.y);
        a0 += ex0 * p0.x + ex1 * q0.x;
        a1 += ex0 * p0.y + ex1 * q0.y;
        a2 += ex0 * p1.x + ex1 * q1.x;
        a3 += ex0 * p1.y + ex1 * q1.y;
    }
    if (i < o1) {
        int e = g_eid[i];
        float ex = expf(g_sc[(size_t)e * NH + h] - smax);
        den += ex;
        uint2 raw = *(const uint2*)(g_vh + (size_t)e * 128 + c4);
        float2 v0 = __bfloat1622float2(*(__nv_bfloat162*)&raw.x);
        float2 v1 = __bfloat1622float2(*(__nv_bfloat162*)&raw.y);
        a0 += ex * v0.x; a1 += ex * v0.y; a2 += ex * v1.x; a3 += ex * v1.y;
    }
    float inv = 1.f / (den + 1e-16f);
    st_bf4(&g_aggh[(size_t)w * 128 + c4],
           make_float4(a0 * inv, a1 * inv, a2 * inv, a3 * inv));
}

// ---------------- launch --------------------------------------------------------
extern "C" void kernel_launch(void* const* d_in, const int* in_sizes, int n_in,
                              void* d_out, int out_size) {
    const float* x     = (const float*)d_in[0];
    const float* t     = (const float*)d_in[1];
    const float* f_ij  = (const float*)d_in[2];
    const float* r_ij  = (const float*)d_in[3];
    const int*   src   = (const int*)d_in[4];
    const int*   dst   = (const int*)d_in[5];
    const float* W_lin = (const float*)d_in[6];
    const float* b_lin = (const float*)d_in[7];
    const float* W_r1  = (const float*)d_in[8];
    const float* b_r1  = (const float*)d_in[9];
    const float* W_r2  = (const float*)d_in[10];
    const float* b_r2  = (const float*)d_in[11];
    const float* Wq    = (const float*)d_in[12];
    const float* bq    = (const float*)d_in[13];
    const float* Wk    = (const float*)d_in[14];
    const float* bk    = (const float*)d_in[15];
    const float* Wv    = (const float*)d_in[16];
    const float* bv    = (const float*)d_in[17];
    const float* Wo    = (const float*)d_in[18];
    const float* bo    = (const float*)d_in[19];
    const float* ln_g  = (const float*)d_in[20];
    const float* ln_b  = (const float*)d_in[21];
    float* out = (float*)d_out;

    bf16 *pWall, *phh, *paggh;
    float *pq;
    cudaGetSymbolAddress((void**)&pWall, g_Wall);
    cudaGetSymbolAddress((void**)&phh, g_hh);
    cudaGetSymbolAddress((void**)&pq,  g_q);
    cudaGetSymbolAddress((void**)&paggh, g_aggh);

    static cudaStream_t s_side = nullptr;
    static cudaEvent_t ev_fork = nullptr, ev_join = nullptr;
    if (s_side == nullptr) {
        cudaStreamCreateWithFlags(&s_side, cudaStreamNonBlocking);
        cudaEventCreateWithFlags(&ev_fork, cudaEventDisableTiming);
        cudaEventCreateWithFlags(&ev_join, cudaEventDisableTiming);
    }

    const int SM_NODE = 128 * 132 * 4 + 2 * (128 * 136 * 2);
    cudaFuncSetAttribute((const void*)node_gemm_h<0, true>, cudaFuncAttributeMaxDynamicSharedMemorySize, SM_NODE);
    cudaFuncSetAttribute((const void*)node_gemm_h<3, true>, cudaFuncAttributeMaxDynamicSharedMemorySize, SM_NODE);
    cudaFuncSetAttribute((const void*)edge_fused_kernel,    cudaFuncAttributeMaxDynamicSharedMemorySize, SMO_TOT);

    const int TB = 256;
    int gridN  = (NNODE * Dm + TB - 1) / TB;
    int gridE  = (NEDGE + TB - 1) / TB;
    int gemmE  = NEDGE / 128;           // 5000
    int gemmN  = (NNODE + 127) / 128;   // 313

    // ---- main stream (round-8 proven schedule) ----
    convert_all_kernel<<<W_TOTAL / 512, 512>>>(W_r1, W_lin, W_r2, Wq, Wk, Wv, Wo);
    add_h_kernel<<<gridN, TB>>>(x, t);           // also inits g_smax

    // ---- fork: CSR build on side stream (independent of GEMM chain) ----
    cudaEventRecord(ev_fork, 0);
    cudaStreamWaitEvent(s_side, ev_fork, 0);
    init_csr_kernel<<<(NNODE + TB - 1) / TB, TB, 0, s_side>>>();
    hist_kernel<<<gridE, TB, 0, s_side>>>(dst);
    scan_kernel<<<1, 1024, 0, s_side>>>();
    idscatter_kernel<<<gridE, TB, 0, s_side>>>(dst);
    cudaEventRecord(ev_join, s_side);

    // ---- main continues ----
    node_gemm_h<0, true><<<gemmN, 512, SM_NODE>>>(phh, pWall + OFF_WQ, bq, pq,
                                                  NNODE, nullptr, nullptr, nullptr);
    edge_fused_kernel<<<gemmE, 512, SMO_TOT>>>(f_ij, r_ij, src, dst,
                                               b_r1, b_lin, b_r2, bk, bv);

    // ---- join, then aggregation + output ----
    cudaStreamWaitEvent(0, ev_join, 0);
    agg_kernel<<<(NNODE * 32 + TB - 1) / TB, TB>>>();
    node_gemm_h<3, true><<<gemmN, 512, SM_NODE>>>(paggh, pWall + OFF_WO, bo, out,
                                                  NNODE, x, ln_g, ln_b);
}